// round 11
// baseline (speedup 1.0000x reference)
#include <cuda_runtime.h>
#include <cuda_bf16.h>

// Problem constants
#define NB 256   // batch (both i and j axes)
#define ND 64    // dim_z
#define NS 32    // samples
#define NPOINTS_PER_D (NB * NS)          // 8192 (j,s) points per dim d
#define P 2                              // points per thread (more warps!)
#define THREADS 128
#define POINTS_PER_BLOCK (THREADS * P)   // 256
#define YTILES (NPOINTS_PER_D / POINTS_PER_BLOCK) // 32
#define GRID_TOTAL (ND * YTILES)         // 2048

// Hybrid split: 192 posteriors via MUFU ex2, 64 via FMA-pipe polynomial exp2,
// interleaved 3:1. At 13.84 warps/SMSP (vs 6.92 in the failed R4/R5 attempts)
// the poly chain latency is covered by other warps.
#define NB_POLY 64
#define NB_MUFU (NB - NB_POLY)           // 192
#define NITER   NB_POLY                  // 64 iterations of (3 MUFU + 1 poly)

typedef unsigned long long u64;

__device__ __forceinline__ float ex2_approx(float x) {
    float r;
    asm("ex2.approx.ftz.f32 %0, %1;" : "=f"(r) : "f"(x));
    return r;
}
__device__ __forceinline__ u64 pk2(float lo, float hi) {
    u64 r; asm("mov.b64 %0, {%1,%2};" : "=l"(r) : "f"(lo), "f"(hi)); return r;
}
__device__ __forceinline__ void upk2(u64 v, float& lo, float& hi) {
    asm("mov.b64 {%0,%1}, %2;" : "=f"(lo), "=f"(hi) : "l"(v));
}
__device__ __forceinline__ u64 fma2_(u64 a, u64 b, u64 c) {
    u64 r; asm("fma.rn.f32x2 %0, %1, %2, %3;" : "=l"(r) : "l"(a), "l"(b), "l"(c)); return r;
}
__device__ __forceinline__ u64 add2_(u64 a, u64 b) {
    u64 r; asm("add.rn.f32x2 %0, %1, %2;" : "=l"(r) : "l"(a), "l"(b)); return r;
}

// Single-launch reduction state (proven in R8): release-store partial,
// acq_rel self-wrapping ticket, last block gathers with __ldcg. No membar.
__device__ float        g_part[GRID_TOTAL];
__device__ unsigned int g_count = 0u;

__global__ __launch_bounds__(THREADS, 14)
void kl_kernel(const float* __restrict__ prior_mean,
               const float* __restrict__ prior_logvar,
               const float* __restrict__ post_mean,
               const float* __restrict__ post_logvar,
               const float* __restrict__ eps,
               float* __restrict__ out)
{
    constexpr float LOG_2PI  = 1.8378770664093453f;
    constexpr float INV_LN2  = 1.4426950408889634f;
    constexpr float LOG_B    = 5.545177444479562f;   // ln(256)
    constexpr float VAR_EPS  = 1.0e-4f;

    // Coefficients replicated pairwise for direct packed-f32x2 loads:
    // sm[i*8 + {0..5}] = {a,a,b,b,c,c}  (32B stride, 16B aligned, uniform idx)
    __shared__ __align__(16) float sm[NB * 8];
    __shared__ float sm_red[THREADS / 32];
    __shared__ int   sm_last;

    const int d = blockIdx.x;
    const int t = threadIdx.x;

    // Per-posterior-i quadratic coefficients in base-2 domain:
    //   w_i(z) = a*z^2 + b*z + c,  a=-inv, b=2*inv*m, c=c0-inv*m^2
#pragma unroll
    for (int r = 0; r < NB / THREADS; r++) {
        int i = t + r * THREADS;
        float m   = post_mean[i * ND + d];
        float lv  = post_logvar[i * ND + d];
        float inv = INV_LN2 / (2.0f * __expf(lv) + VAR_EPS);
        float c0  = (-0.5f * LOG_2PI - 0.5f * lv) * INV_LN2;
        float a = -inv;
        float b = 2.0f * inv * m;
        float c = fmaf(-inv, m * m, c0);
        sm[i * 8 + 0] = a; sm[i * 8 + 1] = a;
        sm[i * 8 + 2] = b; sm[i * 8 + 3] = b;
        sm[i * 8 + 4] = c; sm[i * 8 + 5] = c;
        sm[i * 8 + 6] = 0.0f; sm[i * 8 + 7] = 0.0f;
    }
    __syncthreads();

    // Each thread owns P=2 sample points (j,s) for this d.
    const int qbase = blockIdx.y * POINTS_PER_BLOCK + t;

    float z[P], acc[P];
#pragma unroll
    for (int p = 0; p < P; p++) {
        int q = qbase + p * THREADS;
        int j = q >> 5;
        int s = q & 31;
        float pmj  = post_mean[j * ND + d];
        float plvj = post_logvar[j * ND + d];
        float e    = eps[(j * ND + d) * NS + s];
        z[p]   = fmaf(e, __expf(0.5f * plvj), pmj);
        acc[p] = 0.0f;
    }
    const u64 z01 = pk2(z[0], z[1]);

    // Packed loop-invariant constants.
    const u64 MAGIC2  = pk2(12582912.0f, 12582912.0f);    // 1.5*2^23 (RN round-to-int)
    const u64 NMAGIC2 = pk2(-12582912.0f, -12582912.0f);
    const u64 MONE2   = pk2(-1.0f, -1.0f);
    const u64 ONE2    = pk2(1.0f, 1.0f);
    const u64 C1_2    = pk2(0.6931471806f, 0.6931471806f);
    const u64 C2_2    = pk2(0.2402265070f, 0.2402265070f);
    const u64 C3_2    = pk2(0.0555041087f, 0.0555041087f);

    // Main loop: sum_i 2^{w_i(z_p)}, unstabilized single pass (safe: w<=1.6,
    // the i==j diagonal keeps each sum >= ~e^-14). Body = 3 MUFU-i + 1 poly-i.
    for (int ib = 0; ib < NITER; ib++) {
        // --- 3 posteriors via MUFU ex2 ---
#pragma unroll
        for (int r = 0; r < 3; r++) {
            int i = ib * 3 + r;
            ulonglong2 ab = *(const ulonglong2*)(sm + i * 8);   // (a,a)(b,b)
            u64 c2v       = *(const u64*)(sm + i * 8 + 4);      // (c,c)
            u64 t01 = fma2_(z01, ab.x, ab.y);
            u64 w01 = fma2_(z01, t01, c2v);
            float w0, w1;
            upk2(w01, w0, w1);
            acc[0] += ex2_approx(w0);
            acc[1] += ex2_approx(w1);
        }
        // --- 1 posterior via FMA-pipe exp2 ---
        {
            int i = NB_MUFU + ib;
            ulonglong2 ab = *(const ulonglong2*)(sm + i * 8);
            u64 c2v       = *(const u64*)(sm + i * 8 + 4);
            u64 t01 = fma2_(z01, ab.x, ab.y);
            u64 w01 = fma2_(z01, t01, c2v);

            // clamp so the exponent splice stays in normal range; clamped
            // terms contribute <=2^-123, invisible vs sum floor ~e^-14.
            float wa, wb;
            upk2(w01, wa, wb);
            wa = fmaxf(wa, -124.0f);
            wb = fmaxf(wb, -124.0f);
            u64 vv = pk2(wa, wb);

            u64 tt = add2_(vv, MAGIC2);        // bits(tt)=0x4B400000+k, k=round(w)
            u64 kf = add2_(tt, NMAGIC2);       // k as float
            u64 f  = fma2_(kf, MONE2, vv);     // f = w - k, in [-0.5,0.5]
            u64 q  = fma2_(f, C3_2, C2_2);     // cubic 2^f
            q = fma2_(f, q, C1_2);
            q = fma2_(f, q, ONE2);
            float t0, t1, p0, p1;
            upk2(tt, t0, t1);
            upk2(q,  p0, p1);
            int sb0 = __float_as_int(t0) << 23;   // == k<<23 (magic bits vanish)
            int sb1 = __float_as_int(t1) << 23;
            acc[0] += __int_as_float(__float_as_int(p0) + sb0);
            acc[1] += __int_as_float(__float_as_int(p1) + sb1);
        }
    }

    // Epilogue: lse, prior log-density, density gap.
    float local = 0.0f;
#pragma unroll
    for (int p = 0; p < P; p++) {
        int q = qbase + p * THREADS;
        int j = q >> 5;
        float lse = __logf(acc[p]);   // ln(sum 2^w) = ln(sum e^v)

        float pm  = prior_mean[j * ND + d];
        float plv = prior_logvar[j * ND + d];
        float dd  = z[p] - pm;
        float logprior = -0.5f * LOG_2PI - 0.5f * plv
                         - dd * dd / (2.0f * __expf(plv) + VAR_EPS);

        local += (lse - LOG_B) - logprior;
    }

    // Block reduction.
#pragma unroll
    for (int off = 16; off > 0; off >>= 1)
        local += __shfl_xor_sync(0xffffffffu, local, off);

    int lane = t & 31, warp = t >> 5;
    if (lane == 0) sm_red[warp] = local;
    __syncthreads();

    if (t == 0) {
        float v = sm_red[0] + sm_red[1] + sm_red[2] + sm_red[3];
        const int bid = blockIdx.y * ND + blockIdx.x;   // 0..GRID_TOTAL-1
        asm volatile("st.release.gpu.f32 [%0], %1;"
                     :: "l"(&g_part[bid]), "f"(v) : "memory");
        unsigned int ticket;
        asm volatile("atom.acq_rel.gpu.inc.u32 %0, [%1], %2;"
                     : "=r"(ticket)
                     : "l"(&g_count), "r"((unsigned)(GRID_TOTAL - 1))
                     : "memory");
        sm_last = (ticket == (unsigned)(GRID_TOTAL - 1)) ? 1 : 0;
    }
    __syncthreads();

    if (sm_last) {
        // Last block: all release-stores happened-before its acq_rel ticket.
        // Fixed-order gather (deterministic); __ldcg bypasses L1.
        float s = 0.0f;
#pragma unroll
        for (int r = 0; r < GRID_TOTAL / THREADS; r++)
            s += __ldcg(&g_part[t + r * THREADS]);
#pragma unroll
        for (int off = 16; off > 0; off >>= 1)
            s += __shfl_xor_sync(0xffffffffu, s, off);
        if (lane == 0) sm_red[warp] = s;
        __syncthreads();
        if (t == 0) {
            float tot = sm_red[0] + sm_red[1] + sm_red[2] + sm_red[3];
            out[0] = tot * (1.0f / (float)(NB * NS));
        }
    }
}

extern "C" void kernel_launch(void* const* d_in, const int* in_sizes, int n_in,
                              void* d_out, int out_size) {
    const float* prior_mean   = (const float*)d_in[0];
    const float* prior_logvar = (const float*)d_in[1];
    const float* post_mean    = (const float*)d_in[2];
    const float* post_logvar  = (const float*)d_in[3];
    const float* eps          = (const float*)d_in[4];
    float* out = (float*)d_out;

    dim3 grid(ND, YTILES);
    kl_kernel<<<grid, THREADS>>>(prior_mean, prior_logvar, post_mean,
                                 post_logvar, eps, out);
}

// round 12
// speedup vs baseline: 1.3044x; 1.3044x over previous
#include <cuda_runtime.h>
#include <cuda_bf16.h>

// Problem constants
#define NB 256   // batch (both i and j axes)
#define ND 64    // dim_z
#define NS 32    // samples
#define NPOINTS_PER_D (NB * NS)          // 8192 (j,s) points per dim d
#define P 4                              // points per thread
#define THREADS 128
#define POINTS_PER_BLOCK (THREADS * P)   // 512
#define YTILES (NPOINTS_PER_D / POINTS_PER_BLOCK) // 16
#define GRID_TOTAL (ND * YTILES)         // 1024

__device__ __forceinline__ float ex2_approx(float x) {
    float r;
    asm("ex2.approx.ftz.f32 %0, %1;" : "=f"(r) : "f"(x));
    return r;
}

// Single-launch reduction state. Blocks accumulate into g_acc via atomicAdd
// (relaxed REDG); the acq_rel ticket orders every block's add before the last
// block's acquire-read. The last block writes the scaled result and resets
// g_acc to 0; the ticket self-wraps at GRID_TOTAL-1. State is therefore
// identical at the start of every graph replay. NO membar/threadfence
// (R6: per-CTA MEMBAR.GPU cost ~18us chip-wide). Tail is O(1) work --
// unlike the R8 slot-gather, nothing heavy sits after the last straggler.
__device__ float        g_acc   = 0.0f;
__device__ unsigned int g_count = 0u;

__global__ __launch_bounds__(THREADS, 16)
void kl_kernel(const float* __restrict__ prior_mean,
               const float* __restrict__ prior_logvar,
               const float* __restrict__ post_mean,
               const float* __restrict__ post_logvar,
               const float* __restrict__ eps,
               float* __restrict__ out)
{
    constexpr float LOG_2PI  = 1.8378770664093453f;
    constexpr float INV_LN2  = 1.4426950408889634f;
    constexpr float LOG_B    = 5.545177444479562f;   // ln(256)
    constexpr float VAR_EPS  = 1.0e-4f;

    // Per-posterior-i quadratic coefficients in base-2 domain:
    //   w_i(z) = a*z^2 + b*z + c,  a = -inv, b = 2*inv*m, c = c0 - inv*m^2
    // packed as float4: ONE LDS.128 per i, uniform index -> broadcast.
    __shared__ float4 sm_p[NB];
    __shared__ float  sm_red[THREADS / 32];

    const int d = blockIdx.x;
    const int t = threadIdx.x;

    // Load the 256 posterior (i) params for this dim d (2 per thread).
#pragma unroll
    for (int r = 0; r < NB / THREADS; r++) {
        int i = t + r * THREADS;
        float m   = post_mean[i * ND + d];
        float lv  = post_logvar[i * ND + d];
        float inv = INV_LN2 / (2.0f * __expf(lv) + VAR_EPS);
        float c0  = (-0.5f * LOG_2PI - 0.5f * lv) * INV_LN2;
        float4 pr;
        pr.x = -inv;
        pr.y = 2.0f * inv * m;
        pr.z = fmaf(-inv, m * m, c0);
        pr.w = 0.0f;
        sm_p[i] = pr;
    }
    __syncthreads();

    // Each thread owns P=4 sample points (j,s) for this d.
    const int qbase = blockIdx.y * POINTS_PER_BLOCK + t;

    float z[P];
    float acc[P];
#pragma unroll
    for (int p = 0; p < P; p++) {
        int q = qbase + p * THREADS;
        int j = q >> 5;        // q / NS
        int s = q & 31;        // q % NS
        float pmj  = post_mean[j * ND + d];
        float plvj = post_logvar[j * ND + d];
        float e    = eps[(j * ND + d) * NS + s];
        z[p]   = fmaf(e, __expf(0.5f * plvj), pmj);
        acc[p] = 0.0f;
    }

    // Main loop: sum_i 2^{w_i(z_p)}, unstabilized single pass.
    // Safe: w <= c0/ln2 ~ 1.6 (no overflow); the i==j diagonal term keeps
    // the sum >= ~e^-14 (no total underflow). Sits at ~98% of the MUFU
    // floor (4 EX2 per 8 SMSP-cycles) -- the hard roofline for this math.
#pragma unroll 4
    for (int i = 0; i < NB; i++) {
        float4 pr = sm_p[i];
#pragma unroll
        for (int p = 0; p < P; p++) {
            float t0 = fmaf(z[p], pr.x, pr.y);
            float w  = fmaf(z[p], t0, pr.z);
            acc[p] += ex2_approx(w);
        }
    }

    // Epilogue: lse, prior log-density, density gap.
    float local = 0.0f;
#pragma unroll
    for (int p = 0; p < P; p++) {
        int q = qbase + p * THREADS;
        int j = q >> 5;
        float lse = __logf(acc[p]);   // ln(sum 2^w) = ln(sum e^v)

        float pm  = prior_mean[j * ND + d];
        float plv = prior_logvar[j * ND + d];
        float dd  = z[p] - pm;
        float logprior = -0.5f * LOG_2PI - 0.5f * plv
                         - dd * dd / (2.0f * __expf(plv) + VAR_EPS);

        local += (lse - LOG_B) - logprior;
    }

    // Block reduction.
#pragma unroll
    for (int off = 16; off > 0; off >>= 1)
        local += __shfl_xor_sync(0xffffffffu, local, off);

    int lane = t & 31, warp = t >> 5;
    if (lane == 0) sm_red[warp] = local;
    __syncthreads();

    if (t == 0) {
        float v = sm_red[0] + sm_red[1] + sm_red[2] + sm_red[3];
        // Accumulate (relaxed device-scope reduction, no return).
        atomicAdd(&g_acc, v);
        // Ticket (acq_rel): release orders our add before the increment;
        // acquire on the winning read synchronizes with every other block's
        // release. Wraps to 0 at GRID_TOTAL-1 -> self-resetting.
        unsigned int ticket;
        asm volatile("atom.acq_rel.gpu.inc.u32 %0, [%1], %2;"
                     : "=r"(ticket)
                     : "l"(&g_count), "r"((unsigned)(GRID_TOTAL - 1))
                     : "memory");
        if (ticket == (unsigned)(GRID_TOTAL - 1)) {
            // All 1024 adds happened-before this point.
            float total;
            asm volatile("ld.acquire.gpu.f32 %0, [%1];"
                         : "=f"(total) : "l"(&g_acc) : "memory");
            out[0] = total * (1.0f / (float)(NB * NS));
            // Reset accumulator for the next (graph-replayed) launch; the
            // next launch cannot start until this kernel fully retires.
            asm volatile("st.relaxed.gpu.f32 [%0], %1;"
                         :: "l"(&g_acc), "f"(0.0f) : "memory");
        }
    }
}

extern "C" void kernel_launch(void* const* d_in, const int* in_sizes, int n_in,
                              void* d_out, int out_size) {
    const float* prior_mean   = (const float*)d_in[0];
    const float* prior_logvar = (const float*)d_in[1];
    const float* post_mean    = (const float*)d_in[2];
    const float* post_logvar  = (const float*)d_in[3];
    const float* eps          = (const float*)d_in[4];
    float* out = (float*)d_out;

    dim3 grid(ND, YTILES);
    kl_kernel<<<grid, THREADS>>>(prior_mean, prior_logvar, post_mean,
                                 post_logvar, eps, out);
}

// round 13
// speedup vs baseline: 1.4078x; 1.0793x over previous
#include <cuda_runtime.h>
#include <cuda_bf16.h>
#include <cuda_fp16.h>

// Problem constants
#define NB 256   // batch (both i and j axes)
#define ND 64    // dim_z
#define NS 32    // samples
#define NPOINTS_PER_D (NB * NS)          // 8192 (j,s) points per dim d
#define P 4                              // points per thread
#define THREADS 128
#define POINTS_PER_BLOCK (THREADS * P)   // 512
#define YTILES (NPOINTS_PER_D / POINTS_PER_BLOCK) // 16
#define GRID_TOTAL (ND * YTILES)         // 1024

// fp16 accumulation structure: process i in pairs, flush half2 accumulators
// to fp32 every FLUSH_PAIRS pairs (short fp16 add chains -> bounded error).
#define FLUSH_PAIRS 8                    // 16 i's per flush group
#define NGROUPS (NB / (2 * FLUSH_PAIRS)) // 16

__device__ __forceinline__ unsigned int ex2_h2(unsigned int x) {
    unsigned int r;
    asm("ex2.approx.f16x2 %0, %1;" : "=r"(r) : "r"(x));
    return r;
}

// Single-launch reduction state (validated R11): relaxed atomicAdd into g_acc,
// acq_rel self-wrapping ticket orders all adds before the last block's
// acquire-read. Last block writes the scaled result and resets g_acc -> state
// identical at the start of every graph replay. NO membar/threadfence
// (R6: per-CTA MEMBAR.GPU costs ~18us chip-wide).
__device__ float        g_acc   = 0.0f;
__device__ unsigned int g_count = 0u;

__global__ __launch_bounds__(THREADS, 12)
void kl_kernel(const float* __restrict__ prior_mean,
               const float* __restrict__ prior_logvar,
               const float* __restrict__ post_mean,
               const float* __restrict__ post_logvar,
               const float* __restrict__ eps,
               float* __restrict__ out)
{
    constexpr float LOG_2PI  = 1.8378770664093453f;
    constexpr float INV_LN2  = 1.4426950408889634f;
    constexpr float LOG_B    = 5.545177444479562f;   // ln(256)
    constexpr float VAR_EPS  = 1.0e-4f;

    // Per-posterior-i quadratic coefficients in base-2 domain:
    //   w_i(z) = a*z^2 + b*z + c,  a = -inv, b = 2*inv*m, c = c0 - inv*m^2
    // packed as float4: ONE LDS.128 per i, uniform index -> broadcast.
    __shared__ float4 sm_p[NB];
    __shared__ float  sm_red[THREADS / 32];

    const int d = blockIdx.x;
    const int t = threadIdx.x;

    // Load the 256 posterior (i) params for this dim d (2 per thread).
#pragma unroll
    for (int r = 0; r < NB / THREADS; r++) {
        int i = t + r * THREADS;
        float m   = post_mean[i * ND + d];
        float lv  = post_logvar[i * ND + d];
        float inv = INV_LN2 / (2.0f * __expf(lv) + VAR_EPS);
        float c0  = (-0.5f * LOG_2PI - 0.5f * lv) * INV_LN2;
        float4 pr;
        pr.x = -inv;
        pr.y = 2.0f * inv * m;
        pr.z = fmaf(-inv, m * m, c0);
        pr.w = 0.0f;
        sm_p[i] = pr;
    }
    __syncthreads();

    // Each thread owns P=4 sample points (j,s) for this d.
    const int qbase = blockIdx.y * POINTS_PER_BLOCK + t;

    float z[P];
    float acc[P];
#pragma unroll
    for (int p = 0; p < P; p++) {
        int q = qbase + p * THREADS;
        int j = q >> 5;        // q / NS
        int s = q & 31;        // q % NS
        float pmj  = post_mean[j * ND + d];
        float plvj = post_logvar[j * ND + d];
        float e    = eps[(j * ND + d) * NS + s];
        z[p]   = fmaf(e, __expf(0.5f * plvj), pmj);
        acc[p] = 0.0f;
    }

    // Main loop: sum_i 2^{w_i(z_p)}, unstabilized single pass.
    //   - w computed in FULL fp32 (2 FFMA/elem, no fp16 cancellation risk)
    //   - consecutive (w_i, w_{i+1}) for the same point packed to half2
    //     (1 F2FP), ONE ex2.approx.f16x2 evaluates both (halves MUFU work)
    //   - HADD2 into half2 accumulators; flushed to fp32 every 16 i's
    //     (8-add fp16 chains -> bounded rounding; RN is near-unbiased)
    // Safe: w <= 1.6 (no overflow); fp16 range covers all negative w (deep
    // underflow -> exact 0); the i==j diagonal keeps each sum >= ~e^-14.
    for (int g = 0; g < NGROUPS; g++) {
        __half2 hacc[P];
#pragma unroll
        for (int p = 0; p < P; p++) hacc[p] = __floats2half2_rn(0.0f, 0.0f);

#pragma unroll
        for (int u = 0; u < FLUSH_PAIRS; u++) {
            int i0 = (g * FLUSH_PAIRS + u) * 2;
            float4 prA = sm_p[i0];
            float4 prB = sm_p[i0 + 1];
#pragma unroll
            for (int p = 0; p < P; p++) {
                float tA = fmaf(z[p], prA.x, prA.y);
                float wA = fmaf(z[p], tA, prA.z);
                float tB = fmaf(z[p], prB.x, prB.y);
                float wB = fmaf(z[p], tB, prB.z);
                __half2 hw = __floats2half2_rn(wA, wB);
                unsigned int ebits =
                    ex2_h2(*reinterpret_cast<unsigned int*>(&hw));
                hacc[p] = __hadd2(hacc[p],
                                  *reinterpret_cast<__half2*>(&ebits));
            }
        }
        // Flush: half2 -> fp32 (2 F2F + 2 FADD per point, amortized 1/16 i)
#pragma unroll
        for (int p = 0; p < P; p++)
            acc[p] += __low2float(hacc[p]) + __high2float(hacc[p]);
    }

    // Epilogue: lse, prior log-density, density gap.
    float local = 0.0f;
#pragma unroll
    for (int p = 0; p < P; p++) {
        int q = qbase + p * THREADS;
        int j = q >> 5;
        float lse = __logf(acc[p]);   // ln(sum 2^w) = ln(sum e^v)

        float pm  = prior_mean[j * ND + d];
        float plv = prior_logvar[j * ND + d];
        float dd  = z[p] - pm;
        float logprior = -0.5f * LOG_2PI - 0.5f * plv
                         - dd * dd / (2.0f * __expf(plv) + VAR_EPS);

        local += (lse - LOG_B) - logprior;
    }

    // Block reduction.
#pragma unroll
    for (int off = 16; off > 0; off >>= 1)
        local += __shfl_xor_sync(0xffffffffu, local, off);

    int lane = t & 31, warp = t >> 5;
    if (lane == 0) sm_red[warp] = local;
    __syncthreads();

    if (t == 0) {
        float v = sm_red[0] + sm_red[1] + sm_red[2] + sm_red[3];
        // Accumulate (relaxed device-scope reduction, no return).
        atomicAdd(&g_acc, v);
        // Ticket (acq_rel): release orders our add before the increment;
        // acquire on the winning read synchronizes with all other releases.
        // Wraps to 0 at GRID_TOTAL-1 -> self-resetting across replays.
        unsigned int ticket;
        asm volatile("atom.acq_rel.gpu.inc.u32 %0, [%1], %2;"
                     : "=r"(ticket)
                     : "l"(&g_count), "r"((unsigned)(GRID_TOTAL - 1))
                     : "memory");
        if (ticket == (unsigned)(GRID_TOTAL - 1)) {
            float total;
            asm volatile("ld.acquire.gpu.f32 %0, [%1];"
                         : "=f"(total) : "l"(&g_acc) : "memory");
            out[0] = total * (1.0f / (float)(NB * NS));
            asm volatile("st.relaxed.gpu.f32 [%0], %1;"
                         :: "l"(&g_acc), "f"(0.0f) : "memory");
        }
    }
}

extern "C" void kernel_launch(void* const* d_in, const int* in_sizes, int n_in,
                              void* d_out, int out_size) {
    const float* prior_mean   = (const float*)d_in[0];
    const float* prior_logvar = (const float*)d_in[1];
    const float* post_mean    = (const float*)d_in[2];
    const float* post_logvar  = (const float*)d_in[3];
    const float* eps          = (const float*)d_in[4];
    float* out = (float*)d_out;

    dim3 grid(ND, YTILES);
    kl_kernel<<<grid, THREADS>>>(prior_mean, prior_logvar, post_mean,
                                 post_logvar, eps, out);
}